// round 10
// baseline (speedup 1.0000x reference)
#include <cuda_runtime.h>
#include <math.h>
#include <stdint.h>

#define LSEQ 4096
#define DM   1024
#define NH   16
#define HDIM 64
#define NWIN 8
#define WLEN 512
#define D3   3072
#define KPAD 68
#define VPAD 72

// -------- scratch (allocation-free: device globals) --------
__device__ __align__(256) float g_x1 [LSEQ * DM];
__device__ __align__(256) float g_x1t[LSEQ * DM];
__device__ __align__(256) float g_att[LSEQ * DM];
__device__ __align__(256) float g_x2 [LSEQ * DM];
__device__ __align__(256) float g_qh [NH * LSEQ * KPAD];  // head-major padded Q
__device__ __align__(256) float g_kh [NH * LSEQ * KPAD];  // head-major padded K
__device__ __align__(256) float g_vh [NH * LSEQ * VPAD];  // head-major padded V
__device__ double g_step[DM / 2];
#define WT0 0
#define WT1 (NWIN * D3 * DM)
#define WT2 (WT1 + NWIN * DM * DM)
#define WT3 (WT2 + D3 * DM)
#define WTN (WT3 + DM * DM)
__device__ __align__(256) float g_wt[WTN];

// ---------------- tf32 / mma helpers ----------------
__device__ __forceinline__ void mma_tf32(float c[4], const uint32_t a[4], const uint32_t b[2]) {
    asm volatile(
        "mma.sync.aligned.m16n8k8.row.col.f32.tf32.tf32.f32 "
        "{%0,%1,%2,%3},{%4,%5,%6,%7},{%8,%9},{%0,%1,%2,%3};"
        : "+f"(c[0]), "+f"(c[1]), "+f"(c[2]), "+f"(c[3])
        : "r"(a[0]), "r"(a[1]), "r"(a[2]), "r"(a[3]), "r"(b[0]), "r"(b[1]));
}
__device__ __forceinline__ uint32_t f2tf(float f) {
    uint32_t u;
    asm("cvt.rna.tf32.f32 %0,%1;" : "=r"(u) : "f"(f));
    return u;
}
__device__ __forceinline__ float roundtf(float f) { return __uint_as_float(f2tf(f)); }

__device__ __forceinline__ void ldsm4(uint32_t& r0, uint32_t& r1, uint32_t& r2, uint32_t& r3,
                                      uint32_t addr) {
    asm volatile("ldmatrix.sync.aligned.m8n8.x4.shared.b16 {%0,%1,%2,%3},[%4];"
        : "=r"(r0), "=r"(r1), "=r"(r2), "=r"(r3) : "r"(addr));
}

// ---------------- bulk copy + mbarrier ----------------
__device__ __forceinline__ void bulkcp(uint32_t dst, const void* src, uint32_t bytes, uint32_t mbar) {
    asm volatile(
        "cp.async.bulk.shared::cluster.global.mbarrier::complete_tx::bytes [%0], [%1], %2, [%3];"
        :: "r"(dst), "l"(src), "r"(bytes), "r"(mbar) : "memory");
}
#define MBAR_INIT(mbar, cnt) \
    asm volatile("mbarrier.init.shared.b64 [%0], %1;" :: "r"(mbar), "r"((uint32_t)(cnt)) : "memory")
#define MBAR_EXPECT(mbar, bytes) \
    asm volatile("mbarrier.arrive.expect_tx.shared.b64 _, [%0], %1;" \
        :: "r"(mbar), "r"((uint32_t)(bytes)) : "memory")
#define MBAR_WAIT(mbar, par) do { \
    uint32_t _m = (mbar), _p = (par), _d; \
    asm volatile("{\n\t.reg .pred p;\n\t" \
        "mbarrier.try_wait.parity.acquire.cta.shared::cta.b64 p, [%1], %2;\n\t" \
        "selp.b32 %0, 1, 0, p;\n\t}" : "=r"(_d) : "r"(_m), "r"(_p) : "memory"); \
    if (!_d) { \
        asm volatile("{\n\t.reg .pred P1;\n\t" \
            "WL_%=:\n\t" \
            "mbarrier.try_wait.parity.acquire.cta.shared::cta.b64 P1, [%0], %1, 0x989680;\n\t" \
            "@P1 bra.uni WD_%=;\n\t" \
            "bra.uni WL_%=;\n\t" \
            "WD_%=:\n\t}" :: "r"(_m), "r"(_p) : "memory"); \
    } } while (0)

// FMA-pipe 2^t, clamped
__device__ __forceinline__ float fast_exp2(float t) {
    t = fminf(fmaxf(t, -126.0f), 126.0f);
    float fi = rintf(t);
    float f = t - fi;
    float p = 1.3333558e-3f;
    p = fmaf(p, f, 9.6181291e-3f);
    p = fmaf(p, f, 5.5504108e-2f);
    p = fmaf(p, f, 2.4022650e-1f);
    p = fmaf(p, f, 6.9314718e-1f);
    p = fmaf(p, f, 1.0f);
    return __int_as_float(__float_as_int(p) + ((int)fi << 23));
}

// ---------------- round-to-tf32 pass ----------------
__global__ void round_tf32_kernel(const float4* __restrict__ s, float4* __restrict__ d, int n4) {
    int i = blockIdx.x * blockDim.x + threadIdx.x;
    if (i >= n4) return;
    float4 v = s[i];
    v.x = roundtf(v.x); v.y = roundtf(v.y);
    v.z = roundtf(v.z); v.w = roundtf(v.w);
    d[i] = v;
}

// ---------------- rotary ----------------
__global__ void rotary_table_kernel(const float* __restrict__ rf) {
    int j = threadIdx.x;
    if (j >= DM / 2) return;
    double inv = pow(10000.0, (double)j / (double)(DM / 2));
    g_step[j] = (double)rf[j] / inv;
}

__global__ void rotary_kernel(const float* __restrict__ x,
                              float* __restrict__ xo, float* __restrict__ xt) {
    int idx = blockIdx.x * blockDim.x + threadIdx.x;
    if (idx >= LSEQ * (DM / 2)) return;
    int l = idx / (DM / 2);
    int j = idx % (DM / 2);
    double ang = g_step[j] * (double)l;
    double k = rint(ang * 0.15915494309189535);
    float r = (float)fma(-k, 6.283185307179586, ang);
    float s, c;
    sincosf(r, &s, &c);
    size_t base = (size_t)l * DM;
    float v0 = x[base + j] + c;
    float v1 = x[base + DM / 2 + j] + s;
    xo[base + j]          = v0;
    xo[base + DM / 2 + j] = v1;
    xt[base + j]          = roundtf(v0);
    xt[base + DM / 2 + j] = roundtf(v1);
}

// ---------------- tf32 GEMM with bulk-copy loads ----------------
// qOut != null: write permuted head-major padded q/k/v instead of C.
#define GPAD 36
#define GEMM_BUFB (128 * GPAD * 4)
#define GEMM_MBAR_OFF (4 * GEMM_BUFB)
#define GEMM_SMEM (GEMM_MBAR_OFF + 16)

__global__ __launch_bounds__(256, 2) void gemm_tc(
    const float* __restrict__ A, const float* __restrict__ B,
    const float* __restrict__ bias, const float* __restrict__ resid,
    float* __restrict__ C, int K, int N,
    long aB, long bB, long biasB, long cB, int roundOut,
    float* qOut, float* kOut, float* vOut, int tokStride)
{
    extern __shared__ float sm[];
    float* As = sm;
    float* Bs = sm + 2 * 128 * GPAD;

    int tid = threadIdx.x;
    int lane = tid & 31, wid = tid >> 5;
    int g = lane >> 2, t4 = lane & 3;
    int wm = (wid >> 2) * 64, wn = (wid & 3) * 32;

    const float* Ab = A + (size_t)blockIdx.z * aB + (size_t)blockIdx.y * 128 * K;
    const float* Bb = B + (size_t)blockIdx.z * bB + (size_t)blockIdx.x * 128 * K;

    uint32_t asBase = (uint32_t)__cvta_generic_to_shared(As);
    uint32_t bsBase = (uint32_t)__cvta_generic_to_shared(Bs);
    uint32_t mb = asBase + GEMM_MBAR_OFF;

    uint32_t aLm = asBase + (uint32_t)(((wm + (lane & 15)) * GPAD + 4 * (lane >> 4)) * 4);
    uint32_t bLm = bsBase + (uint32_t)(((wn + (lane & 7) + 8 * (lane >> 4)) * GPAD
                                        + 4 * ((lane >> 3) & 1)) * 4);

    if (tid == 0) { MBAR_INIT(mb, 1); MBAR_INIT(mb + 8, 1); }
    __syncthreads();

    float acc[4][4][4];
#pragma unroll
    for (int i = 0; i < 4; i++)
#pragma unroll
        for (int j = 0; j < 4; j++)
#pragma unroll
            for (int k = 0; k < 4; k++) acc[i][j][k] = 0.f;

    auto issueT = [&](int buf, int t) {
        uint32_t mbb = mb + 8 * buf;
        if (tid == 0) MBAR_EXPECT(mbb, 32768);
        if (tid < 128) {
            bulkcp(asBase + (uint32_t)(buf * GEMM_BUFB + tid * GPAD * 4),
                   Ab + (size_t)tid * K + t * 32, 128, mbb);
        } else {
            int r = tid - 128;
            bulkcp(bsBase + (uint32_t)(buf * GEMM_BUFB + r * GPAD * 4),
                   Bb + (size_t)r * K + t * 32, 128, mbb);
        }
    };

    issueT(0, 0);
    int nk = K >> 5;
    for (int kt = 0; kt < nk; kt++) {
        int cur = kt & 1;
        MBAR_WAIT(mb + 8 * cur, (uint32_t)((kt >> 1) & 1));
        __syncthreads();
        if (kt + 1 < nk) issueT(1 - cur, kt + 1);

        uint32_t ab = aLm + cur * GEMM_BUFB;
        uint32_t bb = bLm + cur * GEMM_BUFB;
#pragma unroll
        for (int c = 0; c < 4; c++) {
            int kc = c * 8;
            uint32_t af[4][4], bf[4][2];
#pragma unroll
            for (int mi = 0; mi < 4; mi++)
                ldsm4(af[mi][0], af[mi][1], af[mi][2], af[mi][3],
                      ab + (uint32_t)((mi * 16 * GPAD + kc) * 4));
            ldsm4(bf[0][0], bf[0][1], bf[1][0], bf[1][1], bb + (uint32_t)(kc * 4));
            ldsm4(bf[2][0], bf[2][1], bf[3][0], bf[3][1],
                  bb + (uint32_t)((16 * GPAD + kc) * 4));
#pragma unroll
            for (int mi = 0; mi < 4; mi++)
#pragma unroll
                for (int ni = 0; ni < 4; ni++)
                    mma_tf32(acc[mi][ni], af[mi], bf[ni]);
        }
    }

    const float* bp = bias + (size_t)blockIdx.z * biasB + blockIdx.x * 128;

    if (qOut) {
        // permuted epilogue: c -> (type, head, dim); token = tokBase + row
        int tokBase = blockIdx.z * tokStride + blockIdx.y * 128;
#pragma unroll
        for (int ni = 0; ni < 4; ni++) {
            int c0 = wn + ni * 8 + 2 * t4;
            int c = blockIdx.x * 128 + c0;
            int type = c >> 10;
            int head = (c >> 6) & 15;
            int dim = c & 63;
            float* basep = (type == 0) ? qOut : (type == 1) ? kOut : vOut;
            int pad = (type == 2) ? VPAD : KPAD;
            float b0 = bp[c0], b1 = bp[c0 + 1];
            size_t hoff = (size_t)head * LSEQ;
#pragma unroll
            for (int mi = 0; mi < 4; mi++) {
                int r0 = wm + mi * 16 + g;
                size_t o0 = (hoff + tokBase + r0) * pad + dim;
                size_t o1 = (hoff + tokBase + r0 + 8) * pad + dim;
                float2 v0 = make_float2(roundtf(acc[mi][ni][0] + b0), roundtf(acc[mi][ni][1] + b1));
                float2 v1 = make_float2(roundtf(acc[mi][ni][2] + b0), roundtf(acc[mi][ni][3] + b1));
                *(float2*)&basep[o0] = v0;
                *(float2*)&basep[o1] = v1;
            }
        }
        return;
    }

    size_t cb = (size_t)blockIdx.z * cB + (size_t)(blockIdx.y * 128) * N + blockIdx.x * 128;
#pragma unroll
    for (int mi = 0; mi < 4; mi++) {
#pragma unroll
        for (int ni = 0; ni < 4; ni++) {
            int r0 = wm + mi * 16 + g;
            int c0 = wn + ni * 8 + 2 * t4;
            float b0 = bp[c0], b1 = bp[c0 + 1];
            size_t o0 = cb + (size_t)r0 * N + c0;
            size_t o1 = cb + (size_t)(r0 + 8) * N + c0;
            float2 v0 = make_float2(acc[mi][ni][0] + b0, acc[mi][ni][1] + b1);
            float2 v1 = make_float2(acc[mi][ni][2] + b0, acc[mi][ni][3] + b1);
            if (resid) {
                float2 r0v = *(const float2*)&resid[o0];
                float2 r1v = *(const float2*)&resid[o1];
                v0.x += r0v.x; v0.y += r0v.y;
                v1.x += r1v.x; v1.y += r1v.y;
            }
            if (roundOut) {
                v0.x = roundtf(v0.x); v0.y = roundtf(v0.y);
                v1.x = roundtf(v1.x); v1.y = roundtf(v1.y);
            }
            *(float2*)&C[o0] = v0;
            *(float2*)&C[o1] = v1;
        }
    }
}

// ---------------- tf32 flash attention: single-bulk-copy tiles ----------------
#define QBYTES (128 * KPAD * 4)
#define KBYTES (64 * KPAD * 4)
#define VBYTES (64 * VPAD * 4)
#define FLASH_MBAR_OFF ((128 * KPAD + 2 * 64 * KPAD + 2 * 64 * VPAD) * 4)
#define FLASH_SMEM (FLASH_MBAR_OFF + 24)

__global__ __launch_bounds__(256, 2) void flash_tc(
    const float* __restrict__ qB, const float* __restrict__ kB,
    const float* __restrict__ vB, float* __restrict__ o, int segLen)
{
    extern __shared__ float sm[];
    float* Ps = sm;                      // [128][KPAD]: Q tile, then P
    float* Vs = sm + 128 * KPAD + 2 * 64 * KPAD;

    int tid = threadIdx.x, lane = tid & 31, wid = tid >> 5;
    int g = lane >> 2, t4 = lane & 3;
    int h = blockIdx.y;
    int segBase = blockIdx.z * segLen;
    int qBase = segBase + blockIdx.x * 128;

    uint32_t psBase = (uint32_t)__cvta_generic_to_shared(Ps);
    uint32_t ksBase = psBase + 128 * KPAD * 4;
    uint32_t vsBase = ksBase + 2 * 64 * KPAD * 4;
    uint32_t mbar   = psBase + FLASH_MBAR_OFF;   // [0]=buf0 [8]=buf1 [16]=Q

    if (tid == 0) {
        MBAR_INIT(mbar, 1); MBAR_INIT(mbar + 8, 1); MBAR_INIT(mbar + 16, 1);
    }
    __syncthreads();

    auto issueKV = [&](int buf, int kt2) {
        if (tid == 0) {
            uint32_t mbb = mbar + 8 * buf;
            MBAR_EXPECT(mbb, KBYTES + VBYTES);
            size_t tok = (size_t)h * LSEQ + segBase + kt2 * 64;
            bulkcp(ksBase + (uint32_t)(buf * KBYTES), kB + tok * KPAD, KBYTES, mbb);
            bulkcp(vsBase + (uint32_t)(buf * VBYTES), vB + tok * VPAD, VBYTES, mbb);
        }
    };

    // Q tile: one bulk copy into Ps
    if (tid == 0) {
        MBAR_EXPECT(mbar + 16, QBYTES);
        bulkcp(psBase, qB + ((size_t)h * LSEQ + qBase) * KPAD, QBYTES, mbar + 16);
    }
    issueKV(0, 0);

    MBAR_WAIT(mbar + 16, 0);
    __syncwarp();
    // lift Q fragments (raw; scale folded into exp2 arg). Warp-private rows.
    uint32_t pLm = psBase + (uint32_t)(((wid * 16 + (lane & 15)) * KPAD + 4 * (lane >> 4)) * 4);
    uint32_t qa[8][4];
#pragma unroll
    for (int kk = 0; kk < 8; kk++)
        ldsm4(qa[kk][0], qa[kk][1], qa[kk][2], qa[kk][3], pLm + (uint32_t)(kk * 8 * 4));
    __syncwarp();

    float oa[8][4];
#pragma unroll
    for (int i = 0; i < 8; i++)
#pragma unroll
        for (int j = 0; j < 4; j++) oa[i][j] = 0.f;
    float l0 = 0.f, l1 = 0.f;

    uint32_t kLm = ksBase + (uint32_t)((((lane & 7) + 8 * (lane >> 4)) * KPAD
                                        + 4 * ((lane >> 3) & 1)) * 4);
    int rr = wid * 16 + g;
    int nT = segLen / 64;
    const float QS = 0.18033688011112042f;   // log2(e)/8, applied post-MMA

    for (int kt = 0; kt < nT; kt++) {
        int buf = kt & 1;
        MBAR_WAIT(mbar + 8 * buf, (uint32_t)((kt >> 1) & 1));
        __syncthreads();
        if (kt + 1 < nT) issueKV(1 - buf, kt + 1);

        // S = Q @ K^T (raw)
        uint32_t kb = kLm + (uint32_t)(buf * KBYTES);
        float s[8][4];
#pragma unroll
        for (int i = 0; i < 8; i++)
#pragma unroll
            for (int j = 0; j < 4; j++) s[i][j] = 0.f;
#pragma unroll
        for (int kk = 0; kk < 8; kk++) {
#pragma unroll
            for (int nip = 0; nip < 4; nip++) {
                uint32_t b0[2], b1[2];
                ldsm4(b0[0], b0[1], b1[0], b1[1],
                      kb + (uint32_t)((nip * 16 * KPAD + kk * 8) * 4));
                mma_tf32(s[2 * nip],     qa[kk], b0);
                mma_tf32(s[2 * nip + 1], qa[kk], b1);
            }
        }

        // no-max softmax in exp2 domain, scale folded
        float rs0 = 0.f, rs1 = 0.f;
#pragma unroll
        for (int ni = 0; ni < 8; ni++) {
            s[ni][0] = fast_exp2(s[ni][0] * QS);
            s[ni][1] = fast_exp2(s[ni][1] * QS);
            s[ni][2] = fast_exp2(s[ni][2] * QS);
            s[ni][3] = fast_exp2(s[ni][3] * QS);
            rs0 += s[ni][0] + s[ni][1];
            rs1 += s[ni][2] + s[ni][3];
        }
        rs0 += __shfl_xor_sync(0xffffffffu, rs0, 1);
        rs0 += __shfl_xor_sync(0xffffffffu, rs0, 2);
        rs1 += __shfl_xor_sync(0xffffffffu, rs1, 1);
        rs1 += __shfl_xor_sync(0xffffffffu, rs1, 2);
        l0 += rs0;
        l1 += rs1;

        // stage P (warp-private rows)
#pragma unroll
        for (int ni = 0; ni < 8; ni++) {
            *(float2*)(Ps + rr * KPAD + ni * 8 + 2 * t4)       = make_float2(s[ni][0], s[ni][1]);
            *(float2*)(Ps + (rr + 8) * KPAD + ni * 8 + 2 * t4) = make_float2(s[ni][2], s[ni][3]);
        }
        __syncwarp();

        // O += P @ V
        const float* Vc = Vs + buf * 64 * VPAD;
#pragma unroll
        for (int kk = 0; kk < 8; kk++) {
            uint32_t a[4];
            ldsm4(a[0], a[1], a[2], a[3], pLm + (uint32_t)(kk * 8 * 4));
#pragma unroll
            for (int ni = 0; ni < 8; ni++) {
                uint32_t b[2];
                b[0] = __float_as_uint(Vc[(kk * 8 + t4) * VPAD + ni * 8 + g]);
                b[1] = __float_as_uint(Vc[(kk * 8 + t4 + 4) * VPAD + ni * 8 + g]);
                mma_tf32(oa[ni], a, b);
            }
        }
    }

    // epilogue: normalize by l, round to tf32, store row-major att
    float inv0 = 1.f / l0, inv1 = 1.f / l1;
#pragma unroll
    for (int ni = 0; ni < 8; ni++) {
        float2 v0 = make_float2(roundtf(oa[ni][0] * inv0), roundtf(oa[ni][1] * inv0));
        float2 v1 = make_float2(roundtf(oa[ni][2] * inv1), roundtf(oa[ni][3] * inv1));
        *(float2*)&o[(size_t)(qBase + rr) * DM + h * HDIM + ni * 8 + 2 * t4]     = v0;
        *(float2*)&o[(size_t)(qBase + rr + 8) * DM + h * HDIM + ni * 8 + 2 * t4] = v1;
    }
}

// ---------------- launcher ----------------
extern "C" void kernel_launch(void* const* d_in, const int* in_sizes, int n_in,
                              void* d_out, int out_size) {
    (void)in_sizes; (void)n_in; (void)out_size;
    const float* x         = (const float*)d_in[0];
    const float* rf        = (const float*)d_in[1];
    const float* w_win_in  = (const float*)d_in[2];
    const float* b_win_in  = (const float*)d_in[3];
    const float* w_win_out = (const float*)d_in[4];
    const float* b_win_out = (const float*)d_in[5];
    const float* w_fin_in  = (const float*)d_in[6];
    const float* b_fin_in  = (const float*)d_in[7];
    const float* w_fin_out = (const float*)d_in[8];
    const float* b_fin_out = (const float*)d_in[9];
    float* out = (float*)d_out;

    float *x1, *x1t, *att, *x2, *wt, *qh, *kh, *vh;
    cudaGetSymbolAddress((void**)&x1,  g_x1);
    cudaGetSymbolAddress((void**)&x1t, g_x1t);
    cudaGetSymbolAddress((void**)&att, g_att);
    cudaGetSymbolAddress((void**)&x2,  g_x2);
    cudaGetSymbolAddress((void**)&wt,  g_wt);
    cudaGetSymbolAddress((void**)&qh,  g_qh);
    cudaGetSymbolAddress((void**)&kh,  g_kh);
    cudaGetSymbolAddress((void**)&vh,  g_vh);

    cudaFuncSetAttribute(gemm_tc,
        cudaFuncAttributeMaxDynamicSharedMemorySize, GEMM_SMEM);
    cudaFuncSetAttribute(flash_tc,
        cudaFuncAttributeMaxDynamicSharedMemorySize, FLASH_SMEM);

    round_tf32_kernel<<<(WT1 - WT0) / 1024, 256>>>((const float4*)w_win_in,  (float4*)(wt + WT0), (WT1 - WT0) / 4);
    round_tf32_kernel<<<(WT2 - WT1) / 1024, 256>>>((const float4*)w_win_out, (float4*)(wt + WT1), (WT2 - WT1) / 4);
    round_tf32_kernel<<<(WT3 - WT2) / 1024, 256>>>((const float4*)w_fin_in,  (float4*)(wt + WT2), (WT3 - WT2) / 4);
    round_tf32_kernel<<<(WTN - WT3) / 1024, 256>>>((const float4*)w_fin_out, (float4*)(wt + WT3), (WTN - WT3) / 4);

    rotary_table_kernel<<<1, DM / 2>>>(rf);
    rotary_kernel<<<(LSEQ * (DM / 2)) / 256, 256>>>(x, x1, x1t);

    // 2. window QKV -> head-major padded q/k/v
    gemm_tc<<<dim3(D3 / 128, WLEN / 128, NWIN), 256, GEMM_SMEM>>>(
        x1t, wt + WT0, b_win_in, nullptr, nullptr,
        DM, D3, (long)WLEN * DM, (long)D3 * DM, (long)D3, 0, 1,
        qh, kh, vh, WLEN);

    // 3. window attention
    flash_tc<<<dim3(WLEN / 128, NH, NWIN), 256, FLASH_SMEM>>>(qh, kh, vh, att, WLEN);

    // 4. window out-proj + residual
    gemm_tc<<<dim3(DM / 128, WLEN / 128, NWIN), 256, GEMM_SMEM>>>(
        att, wt + WT1, b_win_out, x1, x2,
        DM, DM, (long)WLEN * DM, (long)DM * DM, (long)DM, (long)WLEN * DM, 1,
        nullptr, nullptr, nullptr, 0);

    // 5. final QKV -> head-major padded q/k/v
    gemm_tc<<<dim3(D3 / 128, LSEQ / 128, 1), 256, GEMM_SMEM>>>(
        x2, wt + WT2, b_fin_in, nullptr, nullptr,
        DM, D3, 0, 0, 0, 0, 1,
        qh, kh, vh, 0);

    // 6. final attention
    flash_tc<<<dim3(LSEQ / 128, NH, 1), 256, FLASH_SMEM>>>(qh, kh, vh, att, LSEQ);

    // 7. final out-proj
    gemm_tc<<<dim3(DM / 128, LSEQ / 128, 1), 256, GEMM_SMEM>>>(
        att, wt + WT3, b_fin_out, nullptr, out,
        DM, DM, 0, 0, 0, 0, 0,
        nullptr, nullptr, nullptr, 0);
}